// round 16
// baseline (speedup 1.0000x reference)
#include <cuda_runtime.h>
#include <cstdint>

#define BATCH 65536
#define INP 64
#define HID 128
#define NACT 16
#define BM 64
#define NTHR 256

// smem strides (floats); XS/HS ≡ 4 (mod 32); WS=20 (R14-proven conflict-free)
#define XS 68
#define HS 132
#define WS 20
#define WHS 132

// Layout (floats): sH [64x132] at 0 (sX [64x68] ALIASED; x dead after chunk 3),
// 2-buffer 3-gate K=16 ring [384x20] each, biases.
// Tail: h1 -> ring base, head weights -> ring+8448 (disjoint, both in dead ring).
#define RING_OFF 8448
#define BUF_FLOATS (384 * WS)                   // 7680
#define SB_OFF (RING_OFF + 2 * BUF_FLOATS)      // 23808
#define SMEM_FLOATS (SB_OFF + 6 * 128)          // 24576
#define SMEM_BYTES (SMEM_FLOATS * 4)            // 98304 B -> 2 CTAs/SM

__device__ __forceinline__ void cpa16(float* dst, const float* src) {
    unsigned u = (unsigned)__cvta_generic_to_shared(dst);
    asm volatile("cp.async.cg.shared.global [%0], [%1], 16;" ::"r"(u), "l"(src));
}
__device__ __forceinline__ void cpcommit() { asm volatile("cp.async.commit_group;"); }

__device__ __forceinline__ float htanh(float v) {
    float r;
    asm("tanh.approx.f32 %0, %1;" : "=f"(r) : "f"(v));
    return r;
}
__device__ __forceinline__ float fsig(float v) {
    return fmaf(htanh(0.5f * v), 0.5f, 0.5f);
}

#define MMA_TF32(d, a0, a1, a2, a3, b0, b1)                                     \
    asm volatile(                                                               \
        "mma.sync.aligned.m16n8k8.row.col.f32.tf32.tf32.f32 "                   \
        "{%0,%1,%2,%3},{%4,%5,%6,%7},{%8,%9},{%0,%1,%2,%3};"                    \
        : "+f"(d[0]), "+f"(d[1]), "+f"(d[2]), "+f"(d[3])                        \
        : "r"(a0), "r"(a1), "r"(a2), "r"(a3), "r"(b0), "r"(b1))

__device__ __forceinline__ void ldsm4(unsigned r[4], unsigned addr) {
    asm volatile("ldmatrix.sync.aligned.m8n8.x4.shared.b16 {%0,%1,%2,%3}, [%4];"
                 : "=r"(r[0]), "=r"(r[1]), "=r"(r[2]), "=r"(r[3])
                 : "r"(addr));
}

__global__ void __launch_bounds__(NTHR, 2)
lstm_policy_kernel(const float* __restrict__ x,
                   const float* __restrict__ Wih0,
                   const float* __restrict__ bih0,
                   const float* __restrict__ bhh0,
                   const float* __restrict__ Wih1,
                   const float* __restrict__ bih1,
                   const float* __restrict__ bhh1,
                   const float* __restrict__ Wp,
                   const float* __restrict__ bp,
                   const float* __restrict__ Wv,
                   const float* __restrict__ bv,
                   float* __restrict__ out) {
    extern __shared__ float sm[];
    float* sH = sm;                          // [64][132] h0
    float* sX = sm;                          // [64][68]  x, ALIASED (dead after chunk 3)
    float* sW = sm + RING_OFF;               // 2 x [384][20] ring
    float* sH1 = sm + RING_OFF;              // h1 [64][132] over dead ring (tail)
    float* sWH = sm + RING_OFF + 8448;       // head weights [24][132] after h1 (tail)
    float* sB = sm + SB_OFF;

    const int tid = threadIdx.x;
    const int wid = tid >> 5, lane = tid & 31;
    const int g = lane >> 2, tg = lane & 3;
    // 8 warps, each owns a UNIQUE 16-out-col strip x 3 gates; A = all 64 rows
    const int ncolW = wid * 16;
    const int rowbase = blockIdx.x * BM;

    // warp-private slab prefetch for chunk k (0..11): 3 gates x 16 rows x 16 K
    // = 192 f4. Only THIS warp reads its rows -> per-warp wait; NO barriers.
    auto prefSlab = [&](int k) {
        const float* W = (k < 4) ? Wih0 : Wih1;
        int ld = (k < 4) ? INP : HID;
        int koff = ((k < 4) ? k : (k - 4)) * 16;
        float* dst = sW + (k & 1) * BUF_FLOATS;
#pragma unroll
        for (int i = 0; i < 6; i++) {
            int idx = lane + i * 32;  // 192 f4 = 3 gates x 16 rows x 4 c4
            int gate = idx >> 6;
            int rem = idx & 63;
            int r = rem >> 2, c4 = rem & 3;
            int gbase = (gate == 0) ? 0 : (gate == 1 ? 256 : 384);
            int row = ncolW + r;
            cpa16(dst + (gate * 128 + row) * WS + c4 * 4,
                  W + (size_t)(gbase + row) * ld + koff + c4 * 4);
        }
    };

    // ---- prologue: G0 = {x}; G1 = {slab0} ----
    {
        const float* xs = x + (size_t)rowbase * INP;
#pragma unroll
        for (int i = 0; i < 4; i++) {
            int idx = tid + i * NTHR;  // 1024 f4 (64 rows x 16)
            int r = idx >> 4;
            int c4 = idx & 15;
            cpa16(sX + r * XS + c4 * 4, xs + r * INP + c4 * 4);
        }
        cpcommit();  // G0
        prefSlab(0);
        cpcommit();  // G1
    }

    // combined biases (plain stores; covered by barrier 1)
    if (tid < 128) {
        sB[tid] = bih0[tid] + bhh0[tid];
        sB[128 + tid] = bih0[256 + tid] + bhh0[256 + tid];
        sB[256 + tid] = bih0[384 + tid] + bhh0[384 + tid];
        sB[384 + tid] = bih1[tid] + bhh1[tid];
        sB[512 + tid] = bih1[256 + tid] + bhh1[256 + tid];
        sB[640 + tid] = bih1[384 + tid] + bhh1[384 + tid];
    }

    asm volatile("cp.async.wait_group 1;");  // G0 done (x); G1 may pend
    __syncthreads();  // BARRIER 1: x/sB visible

    // ---- LDSM addresses (verified mapping from R7-R9/R14) ----
    const int j8 = lane & 7, sel = lane >> 3;
    const int arow = ((sel & 1) << 3) + j8;
    const int acol = (sel >> 1) << 2;
    const unsigned shBase = (unsigned)__cvta_generic_to_shared(sm);
    const unsigned swBase = shBase + RING_OFF * 4;
    const unsigned aX = shBase + (arow * XS + acol) * 4;
    const unsigned aH = shBase + (arow * HS + acol) * 4;
    // B ldsm4 covers rows [ncolW, ncolW+16) x 8K: bf = {nt0 b0, nt0 b1, nt1 b0, nt1 b1}
    const unsigned bO0 = ((ncolW + ((sel >> 1) << 3) + j8) * WS + ((sel & 1) << 2)) * 4;

    // 3-gate fused accumulators: [gate][mt][nt][ci] = 96 regs (the register bet)
    float acc[3][4][2][4];
#pragma unroll
    for (int gt = 0; gt < 3; gt++)
#pragma unroll
        for (int mt = 0; mt < 4; mt++)
#pragma unroll
            for (int nt = 0; nt < 2; nt++)
#pragma unroll
                for (int ci = 0; ci < 4; ci++) acc[gt][mt][nt][ci] = 0.f;

    // one 3-gate K=16 chunk: 8 A-ldsm4 (loaded ONCE, reused by all 3 gates)
    // + 6 B-ldsm4, 48 MMA
    auto gemmChunk = [&](unsigned aBase, unsigned pitch, unsigned wbase) {
#pragma unroll
        for (int ks = 0; ks < 2; ks++) {
            unsigned af[4][4];
#pragma unroll
            for (int mt = 0; mt < 4; mt++) ldsm4(af[mt], aBase + mt * pitch + ks * 32);
#pragma unroll
            for (int gt = 0; gt < 3; gt++) {
                unsigned bf[4];
                ldsm4(bf, wbase + gt * (128 * WS * 4) + bO0 + ks * 32);
#pragma unroll
                for (int mt = 0; mt < 4; mt++) {
                    MMA_TF32(acc[gt][mt][0], af[mt][0], af[mt][1], af[mt][2], af[mt][3], bf[0], bf[1]);
                    MMA_TF32(acc[gt][mt][1], af[mt][0], af[mt][1], af[mt][2], af[mt][3], bf[2], bf[3]);
                }
            }
        }
    };

    // single-pass epilogue straight from the 3 gate accs
    auto epi = [&](int L) {
#pragma unroll
        for (int mt = 0; mt < 4; mt++)
#pragma unroll
            for (int nt = 0; nt < 2; nt++)
#pragma unroll
                for (int ci = 0; ci < 4; ci++) {
                    int row = mt * 16 + g + ((ci >> 1) << 3);
                    int cc = ncolW + nt * 8 + (tg << 1) + (ci & 1);
                    float iv = acc[0][mt][nt][ci] + sB[L * 384 + cc];
                    float gv = acc[1][mt][nt][ci] + sB[L * 384 + 128 + cc];
                    float ov = acc[2][mt][nt][ci] + sB[L * 384 + 256 + cc];
                    float h = fsig(ov) * htanh(fsig(iv) * htanh(gv));
                    if (L == 0)
                        sH[row * HS + cc] = h;
                    else
                        sH1[row * HS + cc] = h;
                    acc[0][mt][nt][ci] = 0.f;
                    acc[1][mt][nt][ci] = 0.f;
                    acc[2][mt][nt][ci] = 0.f;
                }
    };

    const unsigned pX = 16 * XS * 4, pH = 16 * HS * 4;

    // ---- 12-chunk pipeline; slab k in buf k&1; per-warp waits only ----
#pragma unroll
    for (int k = 0; k < 12; ++k) {
        if (k + 1 < 12) {
            prefSlab(k + 1);  // buf (k+1)&1: this warp's reads ended at gemm(k-1)
            cpcommit();
            asm volatile("cp.async.wait_group 1;");  // slab k complete
        } else {
            asm volatile("cp.async.wait_group 0;");
        }
        unsigned wb = swBase + (k & 1) * (BUF_FLOATS * 4);
        if (k < 4)
            gemmChunk(aX + k * 64, pX, wb);
        else
            gemmChunk(aH + (k - 4) * 64, pH, wb);

        if (k == 3) {         // layer boundary: h0 overwrites aliased sX
            __syncthreads();  // BARRIER 2: all warps done reading x
            epi(0);           // h0 -> sH
            __syncthreads();  // BARRIER 3: h0 visible to all warps
        }
    }

    __syncthreads();  // BARRIER 4: all ring reads done (h1/headW overwrite ring)

    // head weights -> dead ring after h1 region (overlap with h1 epilogue)
#pragma unroll
    for (int idx = tid; idx < 544; idx += NTHR) {  // strided! (R2 lesson)
        int r = idx >> 5, c4 = idx & 31;
        const float* srcp = (r < 16) ? (Wp + r * HID + c4 * 4) : (Wv + c4 * 4);
        cpa16(sWH + r * WHS + c4 * 4, srcp);
    }
    cpcommit();
    epi(1);  // h1 -> ring base
#pragma unroll
    for (int idx = tid; idx < 7 * HID; idx += NTHR) {  // zero-pad head rows 17..23
        int r = 17 + idx / HID, c = idx % HID;
        sWH[r * WHS + c] = 0.f;
    }
    asm volatile("cp.async.wait_group 0;");
    __syncthreads();  // BARRIER 5: h1 + head weights visible

    // ---- heads on tensor cores (warps 0..3; proven code) ----
    float* pol = out;
    float* val = out + (size_t)BATCH * NACT;
    if (wid < 4) {
        float ha[3][4];
#pragma unroll
        for (int nt = 0; nt < 3; nt++)
#pragma unroll
            for (int ci = 0; ci < 4; ci++) ha[nt][ci] = 0.f;
        const unsigned* uA = (const unsigned*)sH1;
        const unsigned* uW = (const unsigned*)sWH;
        const int mrowH = wid * 16;
#pragma unroll
        for (int ks = 0; ks < 16; ks++) {
            const unsigned* bA = uA + (mrowH + g) * HS + ks * 8 + tg;
            unsigned a0 = bA[0], a1 = bA[8 * HS], a2 = bA[4], a3 = bA[8 * HS + 4];
#pragma unroll
            for (int nt = 0; nt < 3; nt++) {
                const unsigned* wb = uW + (nt * 8 + g) * WHS + ks * 8 + tg;
                MMA_TF32(ha[nt], a0, a1, a2, a3, wb[0], wb[4]);
            }
        }
#pragma unroll
        for (int nt = 0; nt < 3; nt++)
#pragma unroll
            for (int ci = 0; ci < 4; ci++) {
                int col = nt * 8 + (tg << 1) + (ci & 1);
                int r = mrowH + g + ((ci >> 1) << 3);
                int gr = rowbase + r;
                if (col < NACT)
                    pol[(size_t)gr * NACT + col] = ha[nt][ci] + bp[col];
                else if (col == NACT)
                    val[gr] = ha[nt][ci] + bv[0];
            }
    }
}

extern "C" void kernel_launch(void* const* d_in, const int* in_sizes, int n_in,
                              void* d_out, int out_size) {
    const float* x    = (const float*)d_in[0];
    const float* Wih0 = (const float*)d_in[1];
    // d_in[2] = Whh0: unused (h=0)
    const float* bih0 = (const float*)d_in[3];
    const float* bhh0 = (const float*)d_in[4];
    const float* Wih1 = (const float*)d_in[5];
    // d_in[6] = Whh1: unused (h=0)
    const float* bih1 = (const float*)d_in[7];
    const float* bhh1 = (const float*)d_in[8];
    const float* Wp   = (const float*)d_in[9];
    const float* bp   = (const float*)d_in[10];
    const float* Wv   = (const float*)d_in[11];
    const float* bv   = (const float*)d_in[12];
    float* out = (float*)d_out;

    cudaFuncSetAttribute(lstm_policy_kernel,
                         cudaFuncAttributeMaxDynamicSharedMemorySize, SMEM_BYTES);

    dim3 grid(BATCH / BM);
    dim3 block(NTHR);
    lstm_policy_kernel<<<grid, block, SMEM_BYTES>>>(
        x, Wih0, bih0, bhh0, Wih1, bih1, bhh1, Wp, bp, Wv, bv, out);
}

// round 17
// speedup vs baseline: 1.1449x; 1.1449x over previous
#include <cuda_runtime.h>
#include <cstdint>

#define BATCH 65536
#define INP 64
#define HID 128
#define NACT 16
#define BM 64
#define NTHR 256
#define GRID 304   // 2 CTAs x 152 SMs (GB300) persistent
#define NT (BATCH / BM)  // 1024 tiles

// smem strides (floats); all ≡ 4 (mod 32) -> conflict-free LDSM row addressing
#define XS 68
#define HS 132
#define WS 36
#define WHS 132

// Layout (floats): sH [64x132] at 0 (sX [64x68] ALIASED; x dead after chunk 3),
// 2-buffer ring [256x36] each (ig slabs 256 rows, o slabs 128), biases.
// Per tile tail: h1 -> ring base, head weights -> ring+8448 (both in dead ring).
#define RING_OFF 8448
#define BUF_FLOATS (256 * 36)                   // 9216
#define SB_OFF (RING_OFF + 2 * BUF_FLOATS)      // 26880
#define SMEM_FLOATS (SB_OFF + 6 * 128)          // 27648
#define SMEM_BYTES (SMEM_FLOATS * 4)            // 110592 B -> 2 CTAs/SM

__device__ __forceinline__ void cpa16(float* dst, const float* src) {
    unsigned u = (unsigned)__cvta_generic_to_shared(dst);
    asm volatile("cp.async.cg.shared.global [%0], [%1], 16;" ::"r"(u), "l"(src));
}
__device__ __forceinline__ void cpcommit() { asm volatile("cp.async.commit_group;"); }

__device__ __forceinline__ float htanh(float v) {
    float r;
    asm("tanh.approx.f32 %0, %1;" : "=f"(r) : "f"(v));
    return r;
}
__device__ __forceinline__ float fsig(float v) {
    return fmaf(htanh(0.5f * v), 0.5f, 0.5f);
}

#define MMA_TF32(d, a0, a1, a2, a3, b0, b1)                                     \
    asm volatile(                                                               \
        "mma.sync.aligned.m16n8k8.row.col.f32.tf32.tf32.f32 "                   \
        "{%0,%1,%2,%3},{%4,%5,%6,%7},{%8,%9},{%0,%1,%2,%3};"                    \
        : "+f"(d[0]), "+f"(d[1]), "+f"(d[2]), "+f"(d[3])                        \
        : "r"(a0), "r"(a1), "r"(a2), "r"(a3), "r"(b0), "r"(b1))

__device__ __forceinline__ void ldsm4(unsigned r[4], unsigned addr) {
    asm volatile("ldmatrix.sync.aligned.m8n8.x4.shared.b16 {%0,%1,%2,%3}, [%4];"
                 : "=r"(r[0]), "=r"(r[1]), "=r"(r[2]), "=r"(r[3])
                 : "r"(addr));
}

__global__ void __launch_bounds__(NTHR, 2)
lstm_policy_kernel(const float* __restrict__ x,
                   const float* __restrict__ Wih0,
                   const float* __restrict__ bih0,
                   const float* __restrict__ bhh0,
                   const float* __restrict__ Wih1,
                   const float* __restrict__ bih1,
                   const float* __restrict__ bhh1,
                   const float* __restrict__ Wp,
                   const float* __restrict__ bp,
                   const float* __restrict__ Wv,
                   const float* __restrict__ bv,
                   float* __restrict__ out) {
    extern __shared__ float sm[];
    float* sH = sm;                           // [64][132] h0
    float* sX = sm;                           // [64][68]  x, ALIASED
    float* sW = sm + RING_OFF;                // 2 x [256][36] ring
    float* sH1 = sm + RING_OFF;               // h1 over dead ring (tile tail)
    float* sWH = sm + RING_OFF + 8448;        // head weights over dead ring (tail)
    float* sB = sm + SB_OFF;

    const int tid = threadIdx.x;
    const int wid = tid >> 5, lane = tid & 31;
    const int g = lane >> 2, tg = lane & 3;
    const int ncolW = wid * 16;  // 8 warps x unique 16-out-col strip (R9/R15 tiling)

    // warp-private slab prefetch for chunk k (0..11); identical to R15.
    auto prefSlab = [&](int k) {
        const float* W = (k < 4) ? Wih0 : Wih1;
        int ld = (k < 4) ? INP : HID;
        int koff = ((k < 4) ? (k & 1) : ((k - 4) & 3)) * 32;
        float* dst = sW + (k & 1) * BUF_FLOATS;
        bool isIG = (k < 2) || (k >= 4 && k < 8);
        if (isIG) {
#pragma unroll
            for (int i = 0; i < 8; i++) {
                int idx = lane + i * 32;
                int gt = idx >> 7;
                int rem = idx & 127;
                int r = rem >> 3, c4 = rem & 7;
                int row = ncolW + r;
                cpa16(dst + (gt * 128 + row) * WS + c4 * 4,
                      W + (size_t)((gt ? 256 : 0) + row) * ld + koff + c4 * 4);
            }
        } else {
#pragma unroll
            for (int i = 0; i < 4; i++) {
                int idx = lane + i * 32;
                int r = idx >> 3, c4 = idx & 7;
                int row = ncolW + r;
                cpa16(dst + row * WS + c4 * 4,
                      W + (size_t)(384 + row) * ld + koff + c4 * 4);
            }
        }
    };
    auto loadX = [&](int t) {
        const float* xs = x + (size_t)t * BM * INP;
#pragma unroll
        for (int i = 0; i < 4; i++) {
            int idx = tid + i * NTHR;  // 1024 f4 (64 rows x 16)
            int r = idx >> 4;
            int c4 = idx & 15;
            cpa16(sX + r * XS + c4 * 4, xs + r * INP + c4 * 4);
        }
    };

    // ---- one-time prologue: x(t0) + biases; then slab0 ----
    loadX(blockIdx.x);
    cpcommit();  // {Gx}
    if (tid < 128) {
        sB[tid] = bih0[tid] + bhh0[tid];
        sB[128 + tid] = bih0[256 + tid] + bhh0[256 + tid];
        sB[256 + tid] = bih0[384 + tid] + bhh0[384 + tid];
        sB[384 + tid] = bih1[tid] + bhh1[tid];
        sB[512 + tid] = bih1[256 + tid] + bhh1[256 + tid];
        sB[640 + tid] = bih1[384 + tid] + bhh1[384 + tid];
    }
    asm volatile("cp.async.wait_group 0;");
    __syncthreads();  // x(t0) + biases visible
    prefSlab(0);
    cpcommit();  // entry invariant: pending = {slab0}

    // ---- LDSM addresses (verified mapping, R7-R15) ----
    const int j8 = lane & 7, sel = lane >> 3;
    const int arow = ((sel & 1) << 3) + j8;
    const int acol = (sel >> 1) << 2;
    const unsigned shBase = (unsigned)__cvta_generic_to_shared(sm);
    const unsigned swBase = shBase + RING_OFF * 4;
    const unsigned aX = shBase + (arow * XS + acol) * 4;
    const unsigned aH = shBase + (arow * HS + acol) * 4;
    const unsigned bO0 = ((ncolW + ((sel >> 1) << 3) + j8) * WS + ((sel & 1) << 2)) * 4;

    float acc[2][4][2][4], sc[4][2][4];
#pragma unroll
    for (int gt = 0; gt < 2; gt++)
#pragma unroll
        for (int mt = 0; mt < 4; mt++)
#pragma unroll
            for (int nt = 0; nt < 2; nt++)
#pragma unroll
                for (int ci = 0; ci < 4; ci++) acc[gt][mt][nt][ci] = 0.f;

    auto gemmIG = [&](unsigned aBase, unsigned pitch, unsigned wbase) {
#pragma unroll
        for (int ks = 0; ks < 4; ks++) {
            unsigned af[4][4];
#pragma unroll
            for (int mt = 0; mt < 4; mt++) ldsm4(af[mt], aBase + mt * pitch + ks * 32);
#pragma unroll
            for (int gt = 0; gt < 2; gt++) {
                unsigned bf[4];
                ldsm4(bf, wbase + gt * (128 * WS * 4) + bO0 + ks * 32);
#pragma unroll
                for (int mt = 0; mt < 4; mt++) {
                    MMA_TF32(acc[gt][mt][0], af[mt][0], af[mt][1], af[mt][2], af[mt][3], bf[0], bf[1]);
                    MMA_TF32(acc[gt][mt][1], af[mt][0], af[mt][1], af[mt][2], af[mt][3], bf[2], bf[3]);
                }
            }
        }
    };
    auto gemmO = [&](unsigned aBase, unsigned pitch, unsigned wbase) {
#pragma unroll
        for (int ks = 0; ks < 4; ks++) {
            unsigned bf[4];
            ldsm4(bf, wbase + bO0 + ks * 32);
#pragma unroll
            for (int mt = 0; mt < 4; mt++) {
                unsigned af[4];
                ldsm4(af, aBase + mt * pitch + ks * 32);
                MMA_TF32(acc[0][mt][0], af[0], af[1], af[2], af[3], bf[0], bf[1]);
                MMA_TF32(acc[0][mt][1], af[0], af[1], af[2], af[3], bf[2], bf[3]);
            }
        }
    };
    auto cStage = [&](int L) {
#pragma unroll
        for (int mt = 0; mt < 4; mt++)
#pragma unroll
            for (int nt = 0; nt < 2; nt++)
#pragma unroll
                for (int ci = 0; ci < 4; ci++) {
                    int cc = ncolW + nt * 8 + (tg << 1) + (ci & 1);
                    float iv = acc[0][mt][nt][ci] + sB[L * 384 + cc];
                    float gv = acc[1][mt][nt][ci] + sB[L * 384 + 128 + cc];
                    sc[mt][nt][ci] = fsig(iv) * htanh(gv);
                    acc[0][mt][nt][ci] = 0.f;
                    acc[1][mt][nt][ci] = 0.f;
                }
    };
    auto epiH = [&](int L) {
#pragma unroll
        for (int mt = 0; mt < 4; mt++)
#pragma unroll
            for (int nt = 0; nt < 2; nt++)
#pragma unroll
                for (int ci = 0; ci < 4; ci++) {
                    int row = mt * 16 + g + ((ci >> 1) << 3);
                    int cc = ncolW + nt * 8 + (tg << 1) + (ci & 1);
                    float ov = acc[0][mt][nt][ci] + sB[L * 384 + 256 + cc];
                    float h = fsig(ov) * htanh(sc[mt][nt][ci]);
                    if (L == 0)
                        sH[row * HS + cc] = h;
                    else
                        sH1[row * HS + cc] = h;
                    acc[0][mt][nt][ci] = 0.f;
                }
    };

    const unsigned pX = 16 * XS * 4, pH = 16 * HS * 4;
    float* pol = out;
    float* val = out + (size_t)BATCH * NACT;

    // ================= persistent tile loop =================
    for (int t = blockIdx.x; t < NT; t += GRID) {
        const int rowbase = t * BM;

        // ---- 12-chunk pipeline (R15-identical; entry pending = {slab0}) ----
#pragma unroll
        for (int k = 0; k < 12; ++k) {
            if (k + 1 < 12) {
                prefSlab(k + 1);
                cpcommit();
                asm volatile("cp.async.wait_group 1;");  // slab k complete
            } else {
                asm volatile("cp.async.wait_group 0;");
            }
            unsigned wb = swBase + (k & 1) * (BUF_FLOATS * 4);
            if (k < 2)
                gemmIG(aX + k * 128, pX, wb);
            else if (k < 4)
                gemmO(aX + (k - 2) * 128, pX, wb);
            else if (k < 8)
                gemmIG(aH + (k - 4) * 128, pH, wb);
            else
                gemmO(aH + (k - 8) * 128, pH, wb);

            if (k == 1) cStage(0);
            else if (k == 3) {        // layer boundary: h0 overwrites aliased sX
                __syncthreads();      // all warps done reading x
                epiH(0);              // h0 -> sH
                __syncthreads();      // h0 visible
            } else if (k == 7) cStage(1);
        }

        __syncthreads();  // BARRIER 4: ring + h0 reads done

        // prefetch next tile's x (into dead h0 region) + head weights (dead ring)
        if (t + GRID < NT) loadX(t + GRID);
#pragma unroll
        for (int idx = tid; idx < 544; idx += NTHR) {  // strided! (R2 lesson)
            int r = idx >> 5, c4 = idx & 31;
            const float* srcp = (r < 16) ? (Wp + r * HID + c4 * 4) : (Wv + c4 * 4);
            cpa16(sWH + r * WHS + c4 * 4, srcp);
        }
        cpcommit();  // {x' + headW}
        epiH(1);     // h1 -> ring base
#pragma unroll
        for (int idx = tid; idx < 7 * HID; idx += NTHR) {  // zero-pad rows 17..23
            int r = 17 + idx / HID, c = idx % HID;
            sWH[r * WHS + c] = 0.f;
        }
        asm volatile("cp.async.wait_group 0;");
        __syncthreads();  // BARRIER 5: h1 + headW + x' drained & visible

        // ---- heads on tensor cores (warps 0..3; proven code) ----
        if (wid < 4) {
            float ha[3][4];
#pragma unroll
            for (int nt = 0; nt < 3; nt++)
#pragma unroll
                for (int ci = 0; ci < 4; ci++) ha[nt][ci] = 0.f;
            const unsigned* uA = (const unsigned*)sH1;
            const unsigned* uW = (const unsigned*)sWH;
            const int mrowH = wid * 16;
#pragma unroll
            for (int ks = 0; ks < 16; ks++) {
                const unsigned* bA = uA + (mrowH + g) * HS + ks * 8 + tg;
                unsigned a0 = bA[0], a1 = bA[8 * HS], a2 = bA[4], a3 = bA[8 * HS + 4];
#pragma unroll
                for (int nt = 0; nt < 3; nt++) {
                    const unsigned* wb = uW + (nt * 8 + g) * WHS + ks * 8 + tg;
                    MMA_TF32(ha[nt], a0, a1, a2, a3, wb[0], wb[4]);
                }
            }
#pragma unroll
            for (int nt = 0; nt < 3; nt++)
#pragma unroll
                for (int ci = 0; ci < 4; ci++) {
                    int col = nt * 8 + (tg << 1) + (ci & 1);
                    int r = mrowH + g + ((ci >> 1) << 3);
                    int gr = rowbase + r;
                    if (col < NACT)
                        pol[(size_t)gr * NACT + col] = ha[nt][ci] + bp[col];
                    else if (col == NACT)
                        val[gr] = ha[nt][ci] + bv[0];
                }
        }

        __syncthreads();  // BARRIER 6: heads done reading h1/sWH (ring reusable)
        if (t + GRID < NT) {
            prefSlab(0);  // next tile's slab0 -> buf0
            cpcommit();   // restore entry invariant: pending = {slab0}
        }
    }
}

extern "C" void kernel_launch(void* const* d_in, const int* in_sizes, int n_in,
                              void* d_out, int out_size) {
    const float* x    = (const float*)d_in[0];
    const float* Wih0 = (const float*)d_in[1];
    // d_in[2] = Whh0: unused (h=0)
    const float* bih0 = (const float*)d_in[3];
    const float* bhh0 = (const float*)d_in[4];
    const float* Wih1 = (const float*)d_in[5];
    // d_in[6] = Whh1: unused (h=0)
    const float* bih1 = (const float*)d_in[7];
    const float* bhh1 = (const float*)d_in[8];
    const float* Wp   = (const float*)d_in[9];
    const float* bp   = (const float*)d_in[10];
    const float* Wv   = (const float*)d_in[11];
    const float* bv   = (const float*)d_in[12];
    float* out = (float*)d_out;

    cudaFuncSetAttribute(lstm_policy_kernel,
                         cudaFuncAttributeMaxDynamicSharedMemorySize, SMEM_BYTES);

    dim3 grid(GRID);
    dim3 block(NTHR);
    lstm_policy_kernel<<<grid, block, SMEM_BYTES>>>(
        x, Wih0, bih0, bhh0, Wih1, bih1, bhh1, Wp, bp, Wv, bv, out);
}